// round 2
// baseline (speedup 1.0000x reference)
#include <cuda_runtime.h>
#include <cstdint>
#include <math.h>

// ============================================================================
// FiLMLSTMCell: B=16384, D_IN=512, H=512
//   z = GN4(cat(x,h) @ W + b); FiLM; LSTM gates; GN1(c_new)*gamma+beta; h_new
// GEMM M=16384, N=2048, K=1024 via mma.sync tf32 (sm_103 PTX target —
// tcgen05.ld/wait are rejected by this build, so tcgen05 is unusable).
// ============================================================================
#define BROWS 16384
#define KDIM  1024
#define NDIM  2048
#define HDIM  512

// Scratch (no allocation allowed in kernel_launch)
__device__ float g_A [(size_t)BROWS * KDIM];   //  64 MB : tf32-rounded cat(x,h)
__device__ float g_WT[(size_t)NDIM  * KDIM];   //   8 MB : tf32-rounded W^T [N,K]
__device__ float g_Z [(size_t)BROWS * NDIM];   // 128 MB : GEMM output z

__device__ __forceinline__ float rna_tf32(float x) {
    uint32_t u;
    asm("cvt.rna.tf32.f32 %0, %1;" : "=r"(u) : "f"(x));
    return __uint_as_float(u);
}

__device__ __forceinline__ uint32_t smem_u32(const void* p) {
    uint32_t a;
    asm("{ .reg .u64 t; cvta.to.shared.u64 t, %1; cvt.u32.u64 %0, t; }"
        : "=r"(a) : "l"(p));
    return a;
}

__device__ __forceinline__ void mma_tf32(float* c,
                                         uint32_t a0, uint32_t a1, uint32_t a2, uint32_t a3,
                                         uint32_t b0, uint32_t b1) {
    asm volatile(
        "mma.sync.aligned.m16n8k8.row.col.f32.tf32.tf32.f32 "
        "{%0,%1,%2,%3}, {%4,%5,%6,%7}, {%8,%9}, {%0,%1,%2,%3};"
        : "+f"(c[0]), "+f"(c[1]), "+f"(c[2]), "+f"(c[3])
        : "r"(a0), "r"(a1), "r"(a2), "r"(a3), "r"(b0), "r"(b1));
}

// ============================================================================
// GEMM: CTA tile 128(M) x 256(N), BK=32, 256 threads (8 warps: 2M x 4N),
// warp tile 64x64, double-buffered cp.async, XOR-swizzled smem.
//   smem word offset for element (row,k): row*32 + (k ^ (4*(row&7)))
//   -> all fragment LDS patterns are bank-conflict-free.
// ============================================================================
#define BM 128
#define BN 256
#define BK 32
#define NCHUNK (KDIM / BK)   // 32

#define A_WORDS (BM * BK)                // 4096
#define B_WORDS (BN * BK)                // 8192
#define SMEM_WORDS (2 * A_WORDS + 2 * B_WORDS + BN)   // 24832
#define GEMM_SMEM  (SMEM_WORDS * 4)                   // 99328 B

__device__ __forceinline__ void load_chunk(uint32_t aBase, uint32_t bBase,
                                           const float* __restrict__ Ag,
                                           const float* __restrict__ Bg,
                                           int tid) {
    // A tile: 128 rows x 8 (16B chunks) = 1024 tasks
    #pragma unroll
    for (int rep = 0; rep < 4; rep++) {
        int idx = rep * 256 + tid;
        int row = idx >> 3, q = idx & 7;
        uint32_t off = (uint32_t)(row * 128 + 16 * (q ^ (row & 7)));
        asm volatile("cp.async.cg.shared.global [%0], [%1], 16;"
                     :: "r"(aBase + off), "l"(Ag + (size_t)row * KDIM + q * 4));
    }
    // B tile: 256 rows x 8 = 2048 tasks
    #pragma unroll
    for (int rep = 0; rep < 8; rep++) {
        int idx = rep * 256 + tid;
        int row = idx >> 3, q = idx & 7;
        uint32_t off = (uint32_t)(row * 128 + 16 * (q ^ (row & 7)));
        asm volatile("cp.async.cg.shared.global [%0], [%1], 16;"
                     :: "r"(bBase + off), "l"(Bg + (size_t)row * KDIM + q * 4));
    }
    asm volatile("cp.async.commit_group;" ::: "memory");
}

__global__ void __launch_bounds__(256, 1)
gemm_mma_kernel(const float* __restrict__ bias) {
    extern __shared__ float sm[];
    float* sBias = sm + 2 * A_WORDS + 2 * B_WORDS;

    const int tid = threadIdx.x, wid = tid >> 5, lane = tid & 31;
    const int g = lane >> 2, l4 = lane & 3;
    const int m0 = blockIdx.y * BM;
    const int n0 = blockIdx.x * BN;
    const int wm = wid & 1, wn = wid >> 1;   // warp tile: m wm*64, n wn*64

    const uint32_t sb = smem_u32(sm);
    const uint32_t aSm[2] = { sb, sb + A_WORDS * 4 };
    const uint32_t bSm[2] = { sb + 2 * A_WORDS * 4, sb + 2 * A_WORDS * 4 + B_WORDS * 4 };

    for (int i = tid; i < BN; i += 256) sBias[i] = bias[n0 + i];

    float acc[4][8][4];
    #pragma unroll
    for (int a = 0; a < 4; a++)
        #pragma unroll
        for (int b = 0; b < 8; b++)
            #pragma unroll
            for (int d = 0; d < 4; d++) acc[a][b][d] = 0.0f;

    const float* Ag = g_A  + (size_t)m0 * KDIM;
    const float* Bg = g_WT + (size_t)n0 * KDIM;

    load_chunk(aSm[0], bSm[0], Ag, Bg, tid);
    load_chunk(aSm[1], bSm[1], Ag + BK, Bg + BK, tid);

    for (int kc = 0; kc < NCHUNK; kc++) {
        const int s = kc & 1;
        if (kc < NCHUNK - 1) {
            asm volatile("cp.async.wait_group 1;" ::: "memory");
        } else {
            asm volatile("cp.async.wait_group 0;" ::: "memory");
        }
        __syncthreads();

        const uint32_t* au = (const uint32_t*)(sm + (size_t)s * 0 ) ;
        // recompute word pointers from bases (aSm/bSm are byte addrs of same array)
        const uint32_t* auw = (const uint32_t*)sm + (size_t)s * A_WORDS;
        const uint32_t* buw = (const uint32_t*)sm + 2 * A_WORDS + (size_t)s * B_WORDS;
        (void)au;

        #pragma unroll
        for (int ks = 0; ks < 4; ks++) {
            const int k0 = ks * 8;
            const int kA0 = k0 + l4, kA1 = k0 + l4 + 4;
            uint32_t afr[4][4];
            #pragma unroll
            for (int ms = 0; ms < 4; ms++) {
                const int r0 = wm * 64 + ms * 16 + g;     // (r0&7) == g
                const int sw = 4 * g;
                afr[ms][0] = auw[(r0    ) * 32 + (kA0 ^ sw)];
                afr[ms][1] = auw[(r0 + 8) * 32 + (kA0 ^ sw)];
                afr[ms][2] = auw[(r0    ) * 32 + (kA1 ^ sw)];
                afr[ms][3] = auw[(r0 + 8) * 32 + (kA1 ^ sw)];
            }
            uint32_t bfr[8][2];
            #pragma unroll
            for (int ns = 0; ns < 8; ns++) {
                const int n = wn * 64 + ns * 8 + g;       // (n&7) == g
                const int sw = 4 * g;
                bfr[ns][0] = buw[n * 32 + (kA0 ^ sw)];
                bfr[ns][1] = buw[n * 32 + (kA1 ^ sw)];
            }
            #pragma unroll
            for (int ms = 0; ms < 4; ms++)
                #pragma unroll
                for (int ns = 0; ns < 8; ns++)
                    mma_tf32(acc[ms][ns], afr[ms][0], afr[ms][1], afr[ms][2], afr[ms][3],
                             bfr[ns][0], bfr[ns][1]);
        }
        __syncthreads();
        if (kc + 2 < NCHUNK)
            load_chunk(aSm[s], bSm[s], Ag + (kc + 2) * BK, Bg + (kc + 2) * BK, tid);
    }

    // Epilogue: + bias, store z
    #pragma unroll
    for (int ms = 0; ms < 4; ms++) {
        const int row = m0 + wm * 64 + ms * 16 + g;
        #pragma unroll
        for (int ns = 0; ns < 8; ns++) {
            const int colL = wn * 64 + ns * 8 + 2 * l4;
            const float b0 = sBias[colL], b1 = sBias[colL + 1];
            float2 v0 = make_float2(acc[ms][ns][0] + b0, acc[ms][ns][1] + b1);
            float2 v1 = make_float2(acc[ms][ns][2] + b0, acc[ms][ns][3] + b1);
            *(float2*)(g_Z + (size_t)row       * NDIM + n0 + colL) = v0;
            *(float2*)(g_Z + (size_t)(row + 8) * NDIM + n0 + colL) = v1;
        }
    }
}

// ============================================================================
// Prep: tf32-round + concat(x,h) -> g_A ; tf32-round + transpose W -> g_WT
// ============================================================================
__global__ void __launch_bounds__(256) prep_A_kernel(const float* __restrict__ x,
                                                     const float* __restrict__ h) {
    const int m = blockIdx.x, t = threadIdx.x;
    float4 v;
    if (t < 128) v = ((const float4*)(x + (size_t)m * 512))[t];
    else         v = ((const float4*)(h + (size_t)m * 512))[t - 128];
    v.x = rna_tf32(v.x); v.y = rna_tf32(v.y);
    v.z = rna_tf32(v.z); v.w = rna_tf32(v.w);
    ((float4*)(g_A + (size_t)m * KDIM))[t] = v;
}

__global__ void prep_W_kernel(const float* __restrict__ W) {
    __shared__ float tile[32][33];
    const int n0 = blockIdx.x * 32, k0 = blockIdx.y * 32;
    const int tx = threadIdx.x, ty = threadIdx.y;  // (32, 8)
    #pragma unroll
    for (int j = 0; j < 32; j += 8)
        tile[ty + j][tx] = rna_tf32(W[(size_t)(k0 + ty + j) * NDIM + n0 + tx]);
    __syncthreads();
    #pragma unroll
    for (int j = 0; j < 32; j += 8)
        g_WT[(size_t)(n0 + ty + j) * KDIM + k0 + tx] = tile[tx][ty + j];
}

// ============================================================================
// Fused tail: GN(4)+FiLM+gates+c_new+GN(1)+h_new, 1 CTA / row
// ============================================================================
__device__ __forceinline__ float sigm(float x) { return 1.0f / (1.0f + expf(-x)); }

__global__ void __launch_bounds__(256) fused_tail_kernel(
    const float* __restrict__ c, const float* __restrict__ u,
    const float* __restrict__ gamma, const float* __restrict__ beta,
    float* __restrict__ outH, float* __restrict__ outC) {
    __shared__ float s_z[2048];
    __shared__ float s_sum[8], s_sq[8], s_sum2[8], s_sq2[8];

    const int row = blockIdx.x;
    const int t = threadIdx.x, w = t >> 5, lane = t & 31;

    const float4* zr = (const float4*)(g_Z + (size_t)row * 2048);
    const float4* ua = (const float4*)(u + (size_t)row * 4096);
    const float4* ub = (const float4*)(u + (size_t)row * 4096 + 2048);

    // Phase A: per-group (4 groups of 512) stats; each warp stays in one group
    float4 z0 = zr[2 * t], z1 = zr[2 * t + 1];
    float sum = z0.x + z0.y + z0.z + z0.w + z1.x + z1.y + z1.z + z1.w;
    float sq  = z0.x * z0.x + z0.y * z0.y + z0.z * z0.z + z0.w * z0.w
              + z1.x * z1.x + z1.y * z1.y + z1.z * z1.z + z1.w * z1.w;
    #pragma unroll
    for (int o = 16; o; o >>= 1) {
        sum += __shfl_xor_sync(0xFFFFFFFFu, sum, o);
        sq  += __shfl_xor_sync(0xFFFFFFFFu, sq, o);
    }
    if (lane == 0) { s_sum[w] = sum; s_sq[w] = sq; }
    __syncthreads();
    const int grp = t >> 6;
    const float mean = (s_sum[2 * grp] + s_sum[2 * grp + 1]) * (1.0f / 512.0f);
    const float var  = (s_sq[2 * grp] + s_sq[2 * grp + 1]) * (1.0f / 512.0f) - mean * mean;
    const float inv  = rsqrtf(var + 1e-5f);

    float4 a0 = ua[2 * t], a1 = ua[2 * t + 1];
    float4 b0 = ub[2 * t], b1 = ub[2 * t + 1];
    float4 o0, o1;
    o0.x = (z0.x - mean) * inv * (1.0f + a0.x) + b0.x;
    o0.y = (z0.y - mean) * inv * (1.0f + a0.y) + b0.y;
    o0.z = (z0.z - mean) * inv * (1.0f + a0.z) + b0.z;
    o0.w = (z0.w - mean) * inv * (1.0f + a0.w) + b0.w;
    o1.x = (z1.x - mean) * inv * (1.0f + a1.x) + b1.x;
    o1.y = (z1.y - mean) * inv * (1.0f + a1.y) + b1.y;
    o1.z = (z1.z - mean) * inv * (1.0f + a1.z) + b1.z;
    o1.w = (z1.w - mean) * inv * (1.0f + a1.w) + b1.w;
    ((float4*)s_z)[2 * t] = o0;
    ((float4*)s_z)[2 * t + 1] = o1;
    __syncthreads();

    // Phase B: gates -> c_new (thread owns channels j, j+1)
    const int j = 2 * t;
    float2 iz = *(const float2*)&s_z[j];
    float2 fz = *(const float2*)&s_z[512 + j];
    float2 gz = *(const float2*)&s_z[1536 + j];
    float2 cv = *(const float2*)(c + (size_t)row * 512 + j);
    float cn0 = sigm(fz.x) * cv.x + sigm(iz.x) * tanhf(gz.x);
    float cn1 = sigm(fz.y) * cv.y + sigm(iz.y) * tanhf(gz.y);
    *(float2*)(outC + (size_t)row * 512 + j) = make_float2(cn0, cn1);

    float sum2 = cn0 + cn1, sq2 = cn0 * cn0 + cn1 * cn1;
    #pragma unroll
    for (int o = 16; o; o >>= 1) {
        sum2 += __shfl_xor_sync(0xFFFFFFFFu, sum2, o);
        sq2  += __shfl_xor_sync(0xFFFFFFFFu, sq2, o);
    }
    if (lane == 0) { s_sum2[w] = sum2; s_sq2[w] = sq2; }
    __syncthreads();

    // Phase C: GN(1) over c_new, then h_new
    float ts = 0.0f, tq = 0.0f;
    #pragma unroll
    for (int k = 0; k < 8; k++) { ts += s_sum2[k]; tq += s_sq2[k]; }
    const float m2 = ts * (1.0f / 512.0f);
    const float v2 = tq * (1.0f / 512.0f) - m2 * m2;
    const float inv2 = rsqrtf(v2 + 1e-5f);
    float2 gm = *(const float2*)(gamma + j);
    float2 bt = *(const float2*)(beta + j);
    float cnn0 = (cn0 - m2) * inv2 * gm.x + bt.x;
    float cnn1 = (cn1 - m2) * inv2 * gm.y + bt.y;
    float2 oz = *(const float2*)&s_z[1024 + j];
    float h0 = sigm(oz.x) * tanhf(cnn0);
    float h1 = sigm(oz.y) * tanhf(cnn1);
    *(float2*)(outH + (size_t)row * 512 + j) = make_float2(h0, h1);
}

// ============================================================================
// kernel_launch
// ============================================================================
extern "C" void kernel_launch(void* const* d_in, const int* in_sizes, int n_in,
                              void* d_out, int out_size) {
    const float* x     = (const float*)d_in[0];
    const float* h     = (const float*)d_in[1];
    const float* c     = (const float*)d_in[2];
    const float* u     = (const float*)d_in[3];
    const float* W     = (const float*)d_in[4];
    const float* blin  = (const float*)d_in[5];
    const float* gamma = (const float*)d_in[6];
    const float* beta  = (const float*)d_in[7];
    float* outH = (float*)d_out;
    float* outC = (float*)d_out + (size_t)BROWS * HDIM;

    cudaFuncSetAttribute(gemm_mma_kernel,
                         cudaFuncAttributeMaxDynamicSharedMemorySize, GEMM_SMEM);

    prep_A_kernel<<<BROWS, 256>>>(x, h);
    prep_W_kernel<<<dim3(NDIM / 32, KDIM / 32), dim3(32, 8)>>>(W);
    gemm_mma_kernel<<<dim3(NDIM / BN, BROWS / BM), 256, GEMM_SMEM>>>(blin);
    fused_tail_kernel<<<BROWS, 256>>>(c, u, gamma, beta, outH, outC);
}

// round 3
// speedup vs baseline: 1.0412x; 1.0412x over previous
#include <cuda_runtime.h>
#include <cstdint>
#include <math.h>

// ============================================================================
// FiLMLSTMCell: B=16384, D_IN=512, H=512
// GEMM M=16384, N=2048, K=1024 via mma.sync tf32 (tcgen05.ld not available at
// this build's PTX target sm_103, so tcgen05 path is impossible).
// A (=cat(x,h)) is fed raw fp32; HW tf32 truncation's systematic scale error
// is cancelled by the downstream GroupNorm.
// ============================================================================
#define BROWS 16384
#define KDIM  1024
#define NDIM  2048
#define HDIM  512

__device__ float g_WT[(size_t)NDIM * KDIM];   //   8 MB : tf32-rounded W^T [N,K]
__device__ float g_Z [(size_t)BROWS * NDIM];  // 128 MB : GEMM output z

__device__ __forceinline__ float rna_tf32(float x) {
    uint32_t u;
    asm("cvt.rna.tf32.f32 %0, %1;" : "=r"(u) : "f"(x));
    return __uint_as_float(u);
}

__device__ __forceinline__ void mma_tf32(float* c,
                                         uint32_t a0, uint32_t a1, uint32_t a2, uint32_t a3,
                                         uint32_t b0, uint32_t b1) {
    asm volatile(
        "mma.sync.aligned.m16n8k8.row.col.f32.tf32.tf32.f32 "
        "{%0,%1,%2,%3}, {%4,%5,%6,%7}, {%8,%9}, {%0,%1,%2,%3};"
        : "+f"(c[0]), "+f"(c[1]), "+f"(c[2]), "+f"(c[3])
        : "r"(a0), "r"(a1), "r"(a2), "r"(a3), "r"(b0), "r"(b1));
}

// ============================================================================
// GEMM: CTA tile 128(M) x 256(N), BK=32, 256 threads (8 warps, 2Mx4N of 64x64),
// 4-stage cp.async pipeline, single __syncthreads per chunk.
// smem word offset for (row,k): row*32 + (k ^ (4*(row&7)))  -> conflict-free.
// ============================================================================
#define BM 128
#define BN 256
#define BK 32
#define NCHUNK (KDIM / BK)   // 32
#define STAGES 4

#define A_WORDS (BM * BK)                 // 4096
#define B_WORDS (BN * BK)                 // 8192
#define B_BASE  (STAGES * A_WORDS)        // 16384
#define BIAS_BASE (B_BASE + STAGES * B_WORDS)  // 49152
#define GEMM_SMEM ((BIAS_BASE + BN) * 4)       // 197632 B

__device__ __forceinline__ void load_chunk(uint32_t aBase, uint32_t bBase,
                                           const float* __restrict__ Asrc,
                                           const float* __restrict__ Bsrc,
                                           int tid) {
    // A tile: 128 rows x 8 (16B chunks); Asrc has row stride 512 (x or h)
    #pragma unroll
    for (int rep = 0; rep < 4; rep++) {
        int idx = rep * 256 + tid;
        int row = idx >> 3, q = idx & 7;
        uint32_t off = (uint32_t)(row * 128 + 16 * (q ^ (row & 7)));
        asm volatile("cp.async.cg.shared.global [%0], [%1], 16;"
                     :: "r"(aBase + off), "l"(Asrc + (size_t)row * 512 + q * 4));
    }
    // B tile: 256 rows x 8; Bsrc row stride KDIM
    #pragma unroll
    for (int rep = 0; rep < 8; rep++) {
        int idx = rep * 256 + tid;
        int row = idx >> 3, q = idx & 7;
        uint32_t off = (uint32_t)(row * 128 + 16 * (q ^ (row & 7)));
        asm volatile("cp.async.cg.shared.global [%0], [%1], 16;"
                     :: "r"(bBase + off), "l"(Bsrc + (size_t)row * KDIM + q * 4));
    }
    asm volatile("cp.async.commit_group;" ::: "memory");
}

__global__ void __launch_bounds__(256, 1)
gemm_mma_kernel(const float* __restrict__ x, const float* __restrict__ h,
                const float* __restrict__ bias) {
    extern __shared__ float sm[];
    float* sBias = sm + BIAS_BASE;

    const int tid = threadIdx.x, wid = tid >> 5, lane = tid & 31;
    const int g = lane >> 2, l4 = lane & 3;
    const int m0 = blockIdx.y * BM;
    const int n0 = blockIdx.x * BN;
    const int wm = wid & 1, wn = wid >> 1;

    uint32_t sb;
    asm("{ .reg .u64 t; cvta.to.shared.u64 t, %1; cvt.u32.u64 %0, t; }"
        : "=r"(sb) : "l"(sm));

    for (int i = tid; i < BN; i += 256) sBias[i] = bias[n0 + i];

    float acc[4][8][4];
    #pragma unroll
    for (int a = 0; a < 4; a++)
        #pragma unroll
        for (int b = 0; b < 8; b++)
            #pragma unroll
            for (int d = 0; d < 4; d++) acc[a][b][d] = 0.0f;

    const float* xRow = x + (size_t)m0 * 512;
    const float* hRow = h + (size_t)m0 * 512;
    const float* Bg   = g_WT + (size_t)n0 * KDIM;

    // A source pointer for chunk kc (each 32-wide chunk lies fully in x or h)
    #define ASRC(kc) ((kc) < 16 ? xRow + (kc) * BK : hRow + ((kc) - 16) * BK)

    // prologue: stages 0..2
    #pragma unroll
    for (int s = 0; s < 3; s++)
        load_chunk(sb + s * A_WORDS * 4, sb + (B_BASE + s * B_WORDS) * 4,
                   ASRC(s), Bg + s * BK, tid);

    for (int kc = 0; kc < NCHUNK; kc++) {
        const int s = kc & 3;
        asm volatile("cp.async.wait_group 2;" ::: "memory");
        __syncthreads();

        if (kc + 3 < NCHUNK) {
            const int sl = (kc + 3) & 3;
            load_chunk(sb + sl * A_WORDS * 4, sb + (B_BASE + sl * B_WORDS) * 4,
                       ASRC(kc + 3), Bg + (kc + 3) * BK, tid);
        }

        const uint32_t* auw = (const uint32_t*)sm + (size_t)s * A_WORDS;
        const uint32_t* buw = (const uint32_t*)sm + B_BASE + (size_t)s * B_WORDS;

        #pragma unroll
        for (int ks = 0; ks < 4; ks++) {
            const int k0 = ks * 8;
            const int kA0 = k0 + l4, kA1 = k0 + l4 + 4;
            const int sw = 4 * g;
            uint32_t afr[4][4];
            #pragma unroll
            for (int ms = 0; ms < 4; ms++) {
                const int r0 = wm * 64 + ms * 16 + g;
                afr[ms][0] = auw[(r0    ) * 32 + (kA0 ^ sw)];
                afr[ms][1] = auw[(r0 + 8) * 32 + (kA0 ^ sw)];
                afr[ms][2] = auw[(r0    ) * 32 + (kA1 ^ sw)];
                afr[ms][3] = auw[(r0 + 8) * 32 + (kA1 ^ sw)];
            }
            uint32_t bfr[8][2];
            #pragma unroll
            for (int ns = 0; ns < 8; ns++) {
                const int n = wn * 64 + ns * 8 + g;
                bfr[ns][0] = buw[n * 32 + (kA0 ^ sw)];
                bfr[ns][1] = buw[n * 32 + (kA1 ^ sw)];
            }
            #pragma unroll
            for (int ms = 0; ms < 4; ms++)
                #pragma unroll
                for (int ns = 0; ns < 8; ns++)
                    mma_tf32(acc[ms][ns], afr[ms][0], afr[ms][1], afr[ms][2], afr[ms][3],
                             bfr[ns][0], bfr[ns][1]);
        }
    }
    #undef ASRC

    // Epilogue: + bias, store z
    #pragma unroll
    for (int ms = 0; ms < 4; ms++) {
        const int row = m0 + wm * 64 + ms * 16 + g;
        #pragma unroll
        for (int ns = 0; ns < 8; ns++) {
            const int colL = wn * 64 + ns * 8 + 2 * l4;
            const float b0 = sBias[colL], b1 = sBias[colL + 1];
            float2 v0 = make_float2(acc[ms][ns][0] + b0, acc[ms][ns][1] + b1);
            float2 v1 = make_float2(acc[ms][ns][2] + b0, acc[ms][ns][3] + b1);
            *(float2*)(g_Z + (size_t)row       * NDIM + n0 + colL) = v0;
            *(float2*)(g_Z + (size_t)(row + 8) * NDIM + n0 + colL) = v1;
        }
    }
}

// ============================================================================
// Prep: tf32-round + transpose W -> g_WT  [N,K]
// ============================================================================
__global__ void prep_W_kernel(const float* __restrict__ W) {
    __shared__ float tile[32][33];
    const int n0 = blockIdx.x * 32, k0 = blockIdx.y * 32;
    const int tx = threadIdx.x, ty = threadIdx.y;  // (32, 8)
    #pragma unroll
    for (int j = 0; j < 32; j += 8)
        tile[ty + j][tx] = rna_tf32(W[(size_t)(k0 + ty + j) * NDIM + n0 + tx]);
    __syncthreads();
    #pragma unroll
    for (int j = 0; j < 32; j += 8)
        g_WT[(size_t)(n0 + ty + j) * KDIM + k0 + tx] = tile[tx][ty + j];
}

// ============================================================================
// Fused tail: GN(4)+FiLM+gates+c_new+GN(1)+h_new, 1 CTA / row (DRAM 77.8%)
// ============================================================================
__device__ __forceinline__ float sigm(float x) { return 1.0f / (1.0f + expf(-x)); }

__global__ void __launch_bounds__(256) fused_tail_kernel(
    const float* __restrict__ c, const float* __restrict__ u,
    const float* __restrict__ gamma, const float* __restrict__ beta,
    float* __restrict__ outH, float* __restrict__ outC) {
    __shared__ float s_z[2048];
    __shared__ float s_sum[8], s_sq[8], s_sum2[8], s_sq2[8];

    const int row = blockIdx.x;
    const int t = threadIdx.x, w = t >> 5, lane = t & 31;

    const float4* zr = (const float4*)(g_Z + (size_t)row * 2048);
    const float4* ua = (const float4*)(u + (size_t)row * 4096);
    const float4* ub = (const float4*)(u + (size_t)row * 4096 + 2048);

    float4 z0 = zr[2 * t], z1 = zr[2 * t + 1];
    float sum = z0.x + z0.y + z0.z + z0.w + z1.x + z1.y + z1.z + z1.w;
    float sq  = z0.x * z0.x + z0.y * z0.y + z0.z * z0.z + z0.w * z0.w
              + z1.x * z1.x + z1.y * z1.y + z1.z * z1.z + z1.w * z1.w;
    #pragma unroll
    for (int o = 16; o; o >>= 1) {
        sum += __shfl_xor_sync(0xFFFFFFFFu, sum, o);
        sq  += __shfl_xor_sync(0xFFFFFFFFu, sq, o);
    }
    if (lane == 0) { s_sum[w] = sum; s_sq[w] = sq; }
    __syncthreads();
    const int grp = t >> 6;
    const float mean = (s_sum[2 * grp] + s_sum[2 * grp + 1]) * (1.0f / 512.0f);
    const float var  = (s_sq[2 * grp] + s_sq[2 * grp + 1]) * (1.0f / 512.0f) - mean * mean;
    const float inv  = rsqrtf(var + 1e-5f);

    float4 a0 = ua[2 * t], a1 = ua[2 * t + 1];
    float4 b0 = ub[2 * t], b1 = ub[2 * t + 1];
    float4 o0, o1;
    o0.x = (z0.x - mean) * inv * (1.0f + a0.x) + b0.x;
    o0.y = (z0.y - mean) * inv * (1.0f + a0.y) + b0.y;
    o0.z = (z0.z - mean) * inv * (1.0f + a0.z) + b0.z;
    o0.w = (z0.w - mean) * inv * (1.0f + a0.w) + b0.w;
    o1.x = (z1.x - mean) * inv * (1.0f + a1.x) + b1.x;
    o1.y = (z1.y - mean) * inv * (1.0f + a1.y) + b1.y;
    o1.z = (z1.z - mean) * inv * (1.0f + a1.z) + b1.z;
    o1.w = (z1.w - mean) * inv * (1.0f + a1.w) + b1.w;
    ((float4*)s_z)[2 * t] = o0;
    ((float4*)s_z)[2 * t + 1] = o1;
    __syncthreads();

    const int j = 2 * t;
    float2 iz = *(const float2*)&s_z[j];
    float2 fz = *(const float2*)&s_z[512 + j];
    float2 gz = *(const float2*)&s_z[1536 + j];
    float2 cv = *(const float2*)(c + (size_t)row * 512 + j);
    float cn0 = sigm(fz.x) * cv.x + sigm(iz.x) * tanhf(gz.x);
    float cn1 = sigm(fz.y) * cv.y + sigm(iz.y) * tanhf(gz.y);
    *(float2*)(outC + (size_t)row * 512 + j) = make_float2(cn0, cn1);

    float sum2 = cn0 + cn1, sq2 = cn0 * cn0 + cn1 * cn1;
    #pragma unroll
    for (int o = 16; o; o >>= 1) {
        sum2 += __shfl_xor_sync(0xFFFFFFFFu, sum2, o);
        sq2  += __shfl_xor_sync(0xFFFFFFFFu, sq2, o);
    }
    if (lane == 0) { s_sum2[w] = sum2; s_sq2[w] = sq2; }
    __syncthreads();

    float ts = 0.0f, tq = 0.0f;
    #pragma unroll
    for (int k = 0; k < 8; k++) { ts += s_sum2[k]; tq += s_sq2[k]; }
    const float m2 = ts * (1.0f / 512.0f);
    const float v2 = tq * (1.0f / 512.0f) - m2 * m2;
    const float inv2 = rsqrtf(v2 + 1e-5f);
    float2 gm = *(const float2*)(gamma + j);
    float2 bt = *(const float2*)(beta + j);
    float cnn0 = (cn0 - m2) * inv2 * gm.x + bt.x;
    float cnn1 = (cn1 - m2) * inv2 * gm.y + bt.y;
    float2 oz = *(const float2*)&s_z[1024 + j];
    float h0 = sigm(oz.x) * tanhf(cnn0);
    float h1 = sigm(oz.y) * tanhf(cnn1);
    *(float2*)(outH + (size_t)row * 512 + j) = make_float2(h0, h1);
}

// ============================================================================
// kernel_launch
// ============================================================================
extern "C" void kernel_launch(void* const* d_in, const int* in_sizes, int n_in,
                              void* d_out, int out_size) {
    const float* x     = (const float*)d_in[0];
    const float* h     = (const float*)d_in[1];
    const float* c     = (const float*)d_in[2];
    const float* u     = (const float*)d_in[3];
    const float* W     = (const float*)d_in[4];
    const float* blin  = (const float*)d_in[5];
    const float* gamma = (const float*)d_in[6];
    const float* beta  = (const float*)d_in[7];
    float* outH = (float*)d_out;
    float* outC = (float*)d_out + (size_t)BROWS * HDIM;

    cudaFuncSetAttribute(gemm_mma_kernel,
                         cudaFuncAttributeMaxDynamicSharedMemorySize, GEMM_SMEM);

    prep_W_kernel<<<dim3(NDIM / 32, KDIM / 32), dim3(32, 8)>>>(W);
    gemm_mma_kernel<<<dim3(NDIM / BN, BROWS / BM), 256, GEMM_SMEM>>>(x, h, blin);
    fused_tail_kernel<<<BROWS, 256>>>(c, u, gamma, beta, outH, outC);
}

// round 4
// speedup vs baseline: 1.5795x; 1.5170x over previous
#include <cuda_runtime.h>
#include <cuda_fp16.h>
#include <cstdint>
#include <math.h>

// ============================================================================
// FiLMLSTMCell: B=16384, D_IN=512, H=512
// GEMM M=16384, N=2048, K=1024 via mma.sync m16n8k16 fp16 (f32 accum).
// fp16 mantissa (10 bits) == tf32 mantissa -> same numerical quality as the
// passing tf32 build (rel_err 2.5e-4), at 2x MACs per HMMA instruction.
// tcgen05 path impossible (build targets plain sm_103; tcgen05.ld rejected).
// ============================================================================
#define BROWS 16384
#define KDIM  1024
#define NDIM  2048
#define HDIM  512

__device__ __half g_Ah [(size_t)BROWS * KDIM];  // 32 MB : fp16 cat(x,h)
__device__ __half g_WTh[(size_t)NDIM * KDIM];   //  4 MB : fp16 W^T [N,K]
__device__ float  g_Z  [(size_t)BROWS * NDIM];  // 128 MB : GEMM output z

__device__ __forceinline__ void mma_f16(float* c,
                                        uint32_t a0, uint32_t a1, uint32_t a2, uint32_t a3,
                                        uint32_t b0, uint32_t b1) {
    asm volatile(
        "mma.sync.aligned.m16n8k16.row.col.f32.f16.f16.f32 "
        "{%0,%1,%2,%3}, {%4,%5,%6,%7}, {%8,%9}, {%0,%1,%2,%3};"
        : "+f"(c[0]), "+f"(c[1]), "+f"(c[2]), "+f"(c[3])
        : "r"(a0), "r"(a1), "r"(a2), "r"(a3), "r"(b0), "r"(b1));
}

// ============================================================================
// GEMM: CTA tile 128(M) x 256(N), BK=64 halves (128B rows), 256 threads
// (8 warps, 2Mx4N, warp tile 64x64), 3-stage cp.async pipeline.
// smem 32-bit-word offset for (row, kpair): row*32 + (kp ^ (4*(row&7)))
// -> identical conflict-free swizzle as the tf32 build (word = fp16 pair).
// ============================================================================
#define BM 128
#define BN 256
#define BKH 64                    // K halves per chunk
#define NCHUNK (KDIM / BKH)       // 16
#define STAGES 3

#define A_WORDS (BM * BKH / 2)                 // 4096 (32-bit words)
#define B_WORDS (BN * BKH / 2)                 // 8192
#define B_BASE  (STAGES * A_WORDS)             // 12288
#define BIAS_BASE (B_BASE + STAGES * B_WORDS)  // 36864
#define GEMM_SMEM ((BIAS_BASE + BN) * 4)       // 148480 B

__device__ __forceinline__ void load_chunk(uint32_t aBase, uint32_t bBase,
                                           const __half* __restrict__ Asrc,
                                           const __half* __restrict__ Bsrc,
                                           int tid) {
    // A tile: 128 rows x 8 (16B = 8-half chunks) = 1024 tasks
    #pragma unroll
    for (int rep = 0; rep < 4; rep++) {
        int idx = rep * 256 + tid;
        int row = idx >> 3, q = idx & 7;
        uint32_t off = (uint32_t)(row * 128 + 16 * (q ^ (row & 7)));
        asm volatile("cp.async.cg.shared.global [%0], [%1], 16;"
                     :: "r"(aBase + off), "l"(Asrc + (size_t)row * KDIM + q * 8));
    }
    // B tile: 256 rows x 8 = 2048 tasks
    #pragma unroll
    for (int rep = 0; rep < 8; rep++) {
        int idx = rep * 256 + tid;
        int row = idx >> 3, q = idx & 7;
        uint32_t off = (uint32_t)(row * 128 + 16 * (q ^ (row & 7)));
        asm volatile("cp.async.cg.shared.global [%0], [%1], 16;"
                     :: "r"(bBase + off), "l"(Bsrc + (size_t)row * KDIM + q * 8));
    }
    asm volatile("cp.async.commit_group;" ::: "memory");
}

__global__ void __launch_bounds__(256, 1)
gemm_mma_kernel(const float* __restrict__ bias) {
    extern __shared__ float sm[];
    float* sBias = sm + BIAS_BASE;

    const int tid = threadIdx.x, wid = tid >> 5, lane = tid & 31;
    const int g = lane >> 2, l4 = lane & 3;
    const int m0 = blockIdx.y * BM;
    const int n0 = blockIdx.x * BN;
    const int wm = wid & 1, wn = wid >> 1;

    uint32_t sb;
    asm("{ .reg .u64 t; cvta.to.shared.u64 t, %1; cvt.u32.u64 %0, t; }"
        : "=r"(sb) : "l"(sm));

    for (int i = tid; i < BN; i += 256) sBias[i] = bias[n0 + i];

    float acc[4][8][4];
    #pragma unroll
    for (int a = 0; a < 4; a++)
        #pragma unroll
        for (int b = 0; b < 8; b++)
            #pragma unroll
            for (int d = 0; d < 4; d++) acc[a][b][d] = 0.0f;

    const __half* Ag = g_Ah  + (size_t)m0 * KDIM;
    const __half* Bg = g_WTh + (size_t)n0 * KDIM;

    // prologue: stages 0,1
    load_chunk(sb, sb + B_BASE * 4, Ag, Bg, tid);
    load_chunk(sb + A_WORDS * 4, sb + (B_BASE + B_WORDS) * 4,
               Ag + BKH, Bg + BKH, tid);

    for (int kc = 0; kc < NCHUNK; kc++) {
        const int s = kc % 3;
        asm volatile("cp.async.wait_group 1;" ::: "memory");
        __syncthreads();

        if (kc + 2 < NCHUNK) {
            const int sl = (kc + 2) % 3;
            load_chunk(sb + sl * A_WORDS * 4, sb + (B_BASE + sl * B_WORDS) * 4,
                       Ag + (kc + 2) * BKH, Bg + (kc + 2) * BKH, tid);
        }

        const uint32_t* auw = (const uint32_t*)sm + (size_t)s * A_WORDS;
        const uint32_t* buw = (const uint32_t*)sm + B_BASE + (size_t)s * B_WORDS;

        // 4 k16 steps per 64-half chunk; kpair index 0..31 per row
        #pragma unroll
        for (int ks = 0; ks < 4; ks++) {
            const int kA0 = ks * 8 + l4, kA1 = ks * 8 + l4 + 4;
            const int sw = 4 * g;
            uint32_t afr[4][4];
            #pragma unroll
            for (int ms = 0; ms < 4; ms++) {
                const int r0 = wm * 64 + ms * 16 + g;
                afr[ms][0] = auw[(r0    ) * 32 + (kA0 ^ sw)];
                afr[ms][1] = auw[(r0 + 8) * 32 + (kA0 ^ sw)];
                afr[ms][2] = auw[(r0    ) * 32 + (kA1 ^ sw)];
                afr[ms][3] = auw[(r0 + 8) * 32 + (kA1 ^ sw)];
            }
            uint32_t bfr[8][2];
            #pragma unroll
            for (int ns = 0; ns < 8; ns++) {
                const int n = wn * 64 + ns * 8 + g;
                bfr[ns][0] = buw[n * 32 + (kA0 ^ sw)];
                bfr[ns][1] = buw[n * 32 + (kA1 ^ sw)];
            }
            #pragma unroll
            for (int ms = 0; ms < 4; ms++)
                #pragma unroll
                for (int ns = 0; ns < 8; ns++)
                    mma_f16(acc[ms][ns], afr[ms][0], afr[ms][1], afr[ms][2], afr[ms][3],
                            bfr[ns][0], bfr[ns][1]);
        }
    }

    // Epilogue: + bias, store z (fp32)
    #pragma unroll
    for (int ms = 0; ms < 4; ms++) {
        const int row = m0 + wm * 64 + ms * 16 + g;
        #pragma unroll
        for (int ns = 0; ns < 8; ns++) {
            const int colL = wn * 64 + ns * 8 + 2 * l4;
            const float b0 = sBias[colL], b1 = sBias[colL + 1];
            float2 v0 = make_float2(acc[ms][ns][0] + b0, acc[ms][ns][1] + b1);
            float2 v1 = make_float2(acc[ms][ns][2] + b0, acc[ms][ns][3] + b1);
            *(float2*)(g_Z + (size_t)row       * NDIM + n0 + colL) = v0;
            *(float2*)(g_Z + (size_t)(row + 8) * NDIM + n0 + colL) = v1;
        }
    }
}

// ============================================================================
// Prep: fp32 -> fp16 concat(x,h) -> g_Ah ; fp32 -> fp16 transpose W -> g_WTh
// ============================================================================
__global__ void __launch_bounds__(256) prep_A_kernel(const float* __restrict__ x,
                                                     const float* __restrict__ h) {
    const int m = blockIdx.x, t = threadIdx.x;
    float4 v;
    if (t < 128) v = ((const float4*)(x + (size_t)m * 512))[t];
    else         v = ((const float4*)(h + (size_t)m * 512))[t - 128];
    __half2 lo = __floats2half2_rn(v.x, v.y);
    __half2 hi = __floats2half2_rn(v.z, v.w);
    uint2 pk = make_uint2(*(uint32_t*)&lo, *(uint32_t*)&hi);
    ((uint2*)(g_Ah + (size_t)m * KDIM))[t] = pk;
}

__global__ void prep_W_kernel(const float* __restrict__ W) {
    __shared__ float tile[32][33];
    const int n0 = blockIdx.x * 32, k0 = blockIdx.y * 32;
    const int tx = threadIdx.x, ty = threadIdx.y;  // (32, 8)
    #pragma unroll
    for (int j = 0; j < 32; j += 8)
        tile[ty + j][tx] = W[(size_t)(k0 + ty + j) * NDIM + n0 + tx];
    __syncthreads();
    #pragma unroll
    for (int j = 0; j < 32; j += 8)
        g_WTh[(size_t)(n0 + ty + j) * KDIM + k0 + tx] = __float2half_rn(tile[tx][ty + j]);
}

// ============================================================================
// Fused tail: GN(4)+FiLM+gates+c_new+GN(1)+h_new, 1 CTA / row (DRAM-bound)
// ============================================================================
__device__ __forceinline__ float sigm(float x) { return 1.0f / (1.0f + expf(-x)); }

__global__ void __launch_bounds__(256) fused_tail_kernel(
    const float* __restrict__ c, const float* __restrict__ u,
    const float* __restrict__ gamma, const float* __restrict__ beta,
    float* __restrict__ outH, float* __restrict__ outC) {
    __shared__ float s_z[2048];
    __shared__ float s_sum[8], s_sq[8], s_sum2[8], s_sq2[8];

    const int row = blockIdx.x;
    const int t = threadIdx.x, w = t >> 5, lane = t & 31;

    const float4* zr = (const float4*)(g_Z + (size_t)row * 2048);
    const float4* ua = (const float4*)(u + (size_t)row * 4096);
    const float4* ub = (const float4*)(u + (size_t)row * 4096 + 2048);

    float4 z0 = zr[2 * t], z1 = zr[2 * t + 1];
    float sum = z0.x + z0.y + z0.z + z0.w + z1.x + z1.y + z1.z + z1.w;
    float sq  = z0.x * z0.x + z0.y * z0.y + z0.z * z0.z + z0.w * z0.w
              + z1.x * z1.x + z1.y * z1.y + z1.z * z1.z + z1.w * z1.w;
    #pragma unroll
    for (int o = 16; o; o >>= 1) {
        sum += __shfl_xor_sync(0xFFFFFFFFu, sum, o);
        sq  += __shfl_xor_sync(0xFFFFFFFFu, sq, o);
    }
    if (lane == 0) { s_sum[w] = sum; s_sq[w] = sq; }
    __syncthreads();
    const int grp = t >> 6;
    const float mean = (s_sum[2 * grp] + s_sum[2 * grp + 1]) * (1.0f / 512.0f);
    const float var  = (s_sq[2 * grp] + s_sq[2 * grp + 1]) * (1.0f / 512.0f) - mean * mean;
    const float inv  = rsqrtf(var + 1e-5f);

    float4 a0 = ua[2 * t], a1 = ua[2 * t + 1];
    float4 b0 = ub[2 * t], b1 = ub[2 * t + 1];
    float4 o0, o1;
    o0.x = (z0.x - mean) * inv * (1.0f + a0.x) + b0.x;
    o0.y = (z0.y - mean) * inv * (1.0f + a0.y) + b0.y;
    o0.z = (z0.z - mean) * inv * (1.0f + a0.z) + b0.z;
    o0.w = (z0.w - mean) * inv * (1.0f + a0.w) + b0.w;
    o1.x = (z1.x - mean) * inv * (1.0f + a1.x) + b1.x;
    o1.y = (z1.y - mean) * inv * (1.0f + a1.y) + b1.y;
    o1.z = (z1.z - mean) * inv * (1.0f + a1.z) + b1.z;
    o1.w = (z1.w - mean) * inv * (1.0f + a1.w) + b1.w;
    ((float4*)s_z)[2 * t] = o0;
    ((float4*)s_z)[2 * t + 1] = o1;
    __syncthreads();

    const int j = 2 * t;
    float2 iz = *(const float2*)&s_z[j];
    float2 fz = *(const float2*)&s_z[512 + j];
    float2 gz = *(const float2*)&s_z[1536 + j];
    float2 cv = *(const float2*)(c + (size_t)row * 512 + j);
    float cn0 = sigm(fz.x) * cv.x + sigm(iz.x) * tanhf(gz.x);
    float cn1 = sigm(fz.y) * cv.y + sigm(iz.y) * tanhf(gz.y);
    *(float2*)(outC + (size_t)row * 512 + j) = make_float2(cn0, cn1);

    float sum2 = cn0 + cn1, sq2 = cn0 * cn0 + cn1 * cn1;
    #pragma unroll
    for (int o = 16; o; o >>= 1) {
        sum2 += __shfl_xor_sync(0xFFFFFFFFu, sum2, o);
        sq2  += __shfl_xor_sync(0xFFFFFFFFu, sq2, o);
    }
    if (lane == 0) { s_sum2[w] = sum2; s_sq2[w] = sq2; }
    __syncthreads();

    float ts = 0.0f, tq = 0.0f;
    #pragma unroll
    for (int k = 0; k < 8; k++) { ts += s_sum2[k]; tq += s_sq2[k]; }
    const float m2 = ts * (1.0f / 512.0f);
    const float v2 = tq * (1.0f / 512.0f) - m2 * m2;
    const float inv2 = rsqrtf(v2 + 1e-5f);
    float2 gm = *(const float2*)(gamma + j);
    float2 bt = *(const float2*)(beta + j);
    float cnn0 = (cn0 - m2) * inv2 * gm.x + bt.x;
    float cnn1 = (cn1 - m2) * inv2 * gm.y + bt.y;
    float2 oz = *(const float2*)&s_z[1024 + j];
    float h0 = sigm(oz.x) * tanhf(cnn0);
    float h1 = sigm(oz.y) * tanhf(cnn1);
    *(float2*)(outH + (size_t)row * 512 + j) = make_float2(h0, h1);
}

// ============================================================================
// kernel_launch
// ============================================================================
extern "C" void kernel_launch(void* const* d_in, const int* in_sizes, int n_in,
                              void* d_out, int out_size) {
    const float* x     = (const float*)d_in[0];
    const float* h     = (const float*)d_in[1];
    const float* c     = (const float*)d_in[2];
    const float* u     = (const float*)d_in[3];
    const float* W     = (const float*)d_in[4];
    const float* blin  = (const float*)d_in[5];
    const float* gamma = (const float*)d_in[6];
    const float* beta  = (const float*)d_in[7];
    float* outH = (float*)d_out;
    float* outC = (float*)d_out + (size_t)BROWS * HDIM;

    cudaFuncSetAttribute(gemm_mma_kernel,
                         cudaFuncAttributeMaxDynamicSharedMemorySize, GEMM_SMEM);

    prep_A_kernel<<<BROWS, 256>>>(x, h);
    prep_W_kernel<<<dim3(NDIM / 32, KDIM / 32), dim3(32, 8)>>>(W);
    gemm_mma_kernel<<<dim3(NDIM / BN, BROWS / BM), 256, GEMM_SMEM>>>(blin);
    fused_tail_kernel<<<BROWS, 256>>>(c, u, gamma, beta, outH, outC);
}

// round 5
// speedup vs baseline: 1.6721x; 1.0586x over previous
#include <cuda_runtime.h>
#include <cuda_fp16.h>
#include <cstdint>
#include <math.h>

// ============================================================================
// FiLMLSTMCell: B=16384, D_IN=512, H=512
// GEMM M=16384, N=2048, K=1024 via mma.sync m16n8k16 fp16 (f32 accum),
// ldmatrix fragment loads, fp16 z intermediate.
// ============================================================================
#define BROWS 16384
#define KDIM  1024
#define NDIM  2048
#define HDIM  512

__device__ __half g_Ah [(size_t)BROWS * KDIM];  // 32 MB : fp16 cat(x,h)
__device__ __half g_WTh[(size_t)NDIM * KDIM];   //  4 MB : fp16 W^T [N,K]
__device__ __half g_Zh [(size_t)BROWS * NDIM];  // 64 MB : fp16 z

__device__ __forceinline__ void mma_f16(float* c,
                                        uint32_t a0, uint32_t a1, uint32_t a2, uint32_t a3,
                                        uint32_t b0, uint32_t b1) {
    asm volatile(
        "mma.sync.aligned.m16n8k16.row.col.f32.f16.f16.f32 "
        "{%0,%1,%2,%3}, {%4,%5,%6,%7}, {%8,%9}, {%0,%1,%2,%3};"
        : "+f"(c[0]), "+f"(c[1]), "+f"(c[2]), "+f"(c[3])
        : "r"(a0), "r"(a1), "r"(a2), "r"(a3), "r"(b0), "r"(b1));
}

__device__ __forceinline__ void ldsm_x4(uint32_t& r0, uint32_t& r1,
                                        uint32_t& r2, uint32_t& r3, uint32_t addr) {
    asm volatile("ldmatrix.sync.aligned.m8n8.x4.shared.b16 {%0,%1,%2,%3}, [%4];"
                 : "=r"(r0), "=r"(r1), "=r"(r2), "=r"(r3) : "r"(addr));
}

// ============================================================================
// GEMM: CTA 128(M) x 256(N), BK=64 halves, 256 threads (8 warps, 2Mx4N,
// warp tile 64x64), 3-stage cp.async.
// smem word offset (row, kp): row*32 + (kp ^ (4*(row&7))) -> conflict-free,
// and 16B row-segments stay contiguous (XOR bits 2..4 only), so ldmatrix works.
// ============================================================================
#define BM 128
#define BN 256
#define BKH 64
#define NCHUNK (KDIM / BKH)       // 16
#define STAGES 3

#define A_WORDS (BM * BKH / 2)                 // 4096
#define B_WORDS (BN * BKH / 2)                 // 8192
#define B_BASE  (STAGES * A_WORDS)             // 12288
#define BIAS_BASE (B_BASE + STAGES * B_WORDS)  // 36864
#define GEMM_SMEM ((BIAS_BASE + BN) * 4)       // 148480 B

__device__ __forceinline__ void load_chunk(uint32_t aBase, uint32_t bBase,
                                           const __half* __restrict__ Asrc,
                                           const __half* __restrict__ Bsrc,
                                           int tid) {
    #pragma unroll
    for (int rep = 0; rep < 4; rep++) {
        int idx = rep * 256 + tid;
        int row = idx >> 3, q = idx & 7;
        uint32_t off = (uint32_t)(row * 128 + 16 * (q ^ (row & 7)));
        asm volatile("cp.async.cg.shared.global [%0], [%1], 16;"
                     :: "r"(aBase + off), "l"(Asrc + (size_t)row * KDIM + q * 8));
    }
    #pragma unroll
    for (int rep = 0; rep < 8; rep++) {
        int idx = rep * 256 + tid;
        int row = idx >> 3, q = idx & 7;
        uint32_t off = (uint32_t)(row * 128 + 16 * (q ^ (row & 7)));
        asm volatile("cp.async.cg.shared.global [%0], [%1], 16;"
                     :: "r"(bBase + off), "l"(Bsrc + (size_t)row * KDIM + q * 8));
    }
    asm volatile("cp.async.commit_group;" ::: "memory");
}

__global__ void __launch_bounds__(256, 1)
gemm_mma_kernel(const float* __restrict__ bias) {
    extern __shared__ float sm[];
    float* sBias = sm + BIAS_BASE;

    const int tid = threadIdx.x, wid = tid >> 5, lane = tid & 31;
    const int g = lane >> 2, l4 = lane & 3;
    const int m0 = blockIdx.y * BM;
    const int n0 = blockIdx.x * BN;
    const int wm = wid & 1, wn = wid >> 1;

    uint32_t sb;
    asm("{ .reg .u64 t; cvta.to.shared.u64 t, %1; cvt.u32.u64 %0, t; }"
        : "=r"(sb) : "l"(sm));

    for (int i = tid; i < BN; i += 256) sBias[i] = bias[n0 + i];

    // ldmatrix per-lane constants. t = lane>>3 (tile), rr = lane&7 (row in tile)
    const int t8 = lane >> 3, rr = lane & 7;
    const int swz = 4 * rr;
    // A: tiles {rows0-7 klo, rows8-15 klo, rows0-7 khi, rows8-15 khi}
    const int rowA = wm * 64 + (t8 & 1) * 8 + rr;     // + ms*16
    const int kselA = (t8 >> 1) * 4;
    // B: tiles {n0-7 klo, n0-7 khi, n8-15 klo, n8-15 khi}
    const int rowB = wn * 64 + (t8 >> 1) * 8 + rr;    // + ns2*16
    const int kselB = (t8 & 1) * 4;

    float acc[4][8][4];
    #pragma unroll
    for (int a = 0; a < 4; a++)
        #pragma unroll
        for (int b = 0; b < 8; b++)
            #pragma unroll
            for (int d = 0; d < 4; d++) acc[a][b][d] = 0.0f;

    const __half* Ag = g_Ah  + (size_t)m0 * KDIM;
    const __half* Bg = g_WTh + (size_t)n0 * KDIM;

    load_chunk(sb, sb + B_BASE * 4, Ag, Bg, tid);
    load_chunk(sb + A_WORDS * 4, sb + (B_BASE + B_WORDS) * 4,
               Ag + BKH, Bg + BKH, tid);

    for (int kc = 0; kc < NCHUNK; kc++) {
        const int s = kc % 3;
        asm volatile("cp.async.wait_group 1;" ::: "memory");
        __syncthreads();

        if (kc + 2 < NCHUNK) {
            const int sl = (kc + 2) % 3;
            load_chunk(sb + sl * A_WORDS * 4, sb + (B_BASE + sl * B_WORDS) * 4,
                       Ag + (kc + 2) * BKH, Bg + (kc + 2) * BKH, tid);
        }

        const uint32_t aSm = sb + (uint32_t)s * A_WORDS * 4;
        const uint32_t bSm = sb + (uint32_t)(B_BASE + s * B_WORDS) * 4;

        #pragma unroll
        for (int ks = 0; ks < 4; ks++) {
            const int kwA = (ks * 8 + kselA) ^ swz;
            const int kwB = (ks * 8 + kselB) ^ swz;
            uint32_t afr[4][4];
            #pragma unroll
            for (int ms = 0; ms < 4; ms++)
                ldsm_x4(afr[ms][0], afr[ms][1], afr[ms][2], afr[ms][3],
                        aSm + 4u * ((rowA + ms * 16) * 32 + kwA));
            uint32_t bfr[8][2];
            #pragma unroll
            for (int ns2 = 0; ns2 < 4; ns2++)
                ldsm_x4(bfr[2 * ns2][0], bfr[2 * ns2][1],
                        bfr[2 * ns2 + 1][0], bfr[2 * ns2 + 1][1],
                        bSm + 4u * ((rowB + ns2 * 16) * 32 + kwB));
            #pragma unroll
            for (int ms = 0; ms < 4; ms++)
                #pragma unroll
                for (int ns = 0; ns < 8; ns++)
                    mma_f16(acc[ms][ns], afr[ms][0], afr[ms][1], afr[ms][2], afr[ms][3],
                            bfr[ns][0], bfr[ns][1]);
        }
    }

    // Epilogue: + bias, fp16 z store
    #pragma unroll
    for (int ms = 0; ms < 4; ms++) {
        const int row = m0 + wm * 64 + ms * 16 + g;
        #pragma unroll
        for (int ns = 0; ns < 8; ns++) {
            const int colL = wn * 64 + ns * 8 + 2 * l4;
            const float b0 = sBias[colL], b1 = sBias[colL + 1];
            __half2 v0 = __floats2half2_rn(acc[ms][ns][0] + b0, acc[ms][ns][1] + b1);
            __half2 v1 = __floats2half2_rn(acc[ms][ns][2] + b0, acc[ms][ns][3] + b1);
            *(__half2*)(g_Zh + (size_t)row       * NDIM + n0 + colL) = v0;
            *(__half2*)(g_Zh + (size_t)(row + 8) * NDIM + n0 + colL) = v1;
        }
    }
}

// ============================================================================
// Prep
// ============================================================================
__global__ void __launch_bounds__(256) prep_A_kernel(const float* __restrict__ x,
                                                     const float* __restrict__ h) {
    const int m = blockIdx.x, t = threadIdx.x;
    float4 v;
    if (t < 128) v = ((const float4*)(x + (size_t)m * 512))[t];
    else         v = ((const float4*)(h + (size_t)m * 512))[t - 128];
    __half2 lo = __floats2half2_rn(v.x, v.y);
    __half2 hi = __floats2half2_rn(v.z, v.w);
    uint2 pk = make_uint2(*(uint32_t*)&lo, *(uint32_t*)&hi);
    ((uint2*)(g_Ah + (size_t)m * KDIM))[t] = pk;
}

__global__ void prep_W_kernel(const float* __restrict__ W) {
    __shared__ float tile[32][33];
    const int n0 = blockIdx.x * 32, k0 = blockIdx.y * 32;
    const int tx = threadIdx.x, ty = threadIdx.y;
    #pragma unroll
    for (int j = 0; j < 32; j += 8)
        tile[ty + j][tx] = W[(size_t)(k0 + ty + j) * NDIM + n0 + tx];
    __syncthreads();
    #pragma unroll
    for (int j = 0; j < 32; j += 8)
        g_WTh[(size_t)(n0 + ty + j) * KDIM + k0 + tx] = __float2half_rn(tile[tx][ty + j]);
}

// ============================================================================
// Fused tail: GN(4)+FiLM+gates+c_new+GN(1)+h_new, 1 CTA / row; z now fp16
// ============================================================================
__device__ __forceinline__ float sigm(float x) { return 1.0f / (1.0f + expf(-x)); }

__global__ void __launch_bounds__(256) fused_tail_kernel(
    const float* __restrict__ c, const float* __restrict__ u,
    const float* __restrict__ gamma, const float* __restrict__ beta,
    float* __restrict__ outH, float* __restrict__ outC) {
    __shared__ float s_z[2048];
    __shared__ float s_sum[8], s_sq[8], s_sum2[8], s_sq2[8];

    const int row = blockIdx.x;
    const int t = threadIdx.x, w = t >> 5, lane = t & 31;

    const uint4* zr = (const uint4*)(g_Zh + (size_t)row * 2048);
    const float4* ua = (const float4*)(u + (size_t)row * 4096);
    const float4* ub = (const float4*)(u + (size_t)row * 4096 + 2048);

    // thread t owns z channels [8t, 8t+8)
    uint4 zp = zr[t];
    float2 zf[4];
    zf[0] = __half22float2(*(__half2*)&zp.x);
    zf[1] = __half22float2(*(__half2*)&zp.y);
    zf[2] = __half22float2(*(__half2*)&zp.z);
    zf[3] = __half22float2(*(__half2*)&zp.w);

    float sum = 0.0f, sq = 0.0f;
    #pragma unroll
    for (int q = 0; q < 4; q++) {
        sum += zf[q].x + zf[q].y;
        sq  += zf[q].x * zf[q].x + zf[q].y * zf[q].y;
    }
    #pragma unroll
    for (int o = 16; o; o >>= 1) {
        sum += __shfl_xor_sync(0xFFFFFFFFu, sum, o);
        sq  += __shfl_xor_sync(0xFFFFFFFFu, sq, o);
    }
    if (lane == 0) { s_sum[w] = sum; s_sq[w] = sq; }
    __syncthreads();
    const int grp = t >> 6;
    const float mean = (s_sum[2 * grp] + s_sum[2 * grp + 1]) * (1.0f / 512.0f);
    const float var  = (s_sq[2 * grp] + s_sq[2 * grp + 1]) * (1.0f / 512.0f) - mean * mean;
    const float inv  = rsqrtf(var + 1e-5f);

    float4 a0 = ua[2 * t], a1 = ua[2 * t + 1];
    float4 b0 = ub[2 * t], b1 = ub[2 * t + 1];
    float4 o0, o1;
    o0.x = (zf[0].x - mean) * inv * (1.0f + a0.x) + b0.x;
    o0.y = (zf[0].y - mean) * inv * (1.0f + a0.y) + b0.y;
    o0.z = (zf[1].x - mean) * inv * (1.0f + a0.z) + b0.z;
    o0.w = (zf[1].y - mean) * inv * (1.0f + a0.w) + b0.w;
    o1.x = (zf[2].x - mean) * inv * (1.0f + a1.x) + b1.x;
    o1.y = (zf[2].y - mean) * inv * (1.0f + a1.y) + b1.y;
    o1.z = (zf[3].x - mean) * inv * (1.0f + a1.z) + b1.z;
    o1.w = (zf[3].y - mean) * inv * (1.0f + a1.w) + b1.w;
    ((float4*)s_z)[2 * t] = o0;
    ((float4*)s_z)[2 * t + 1] = o1;
    __syncthreads();

    const int j = 2 * t;
    float2 iz = *(const float2*)&s_z[j];
    float2 fz = *(const float2*)&s_z[512 + j];
    float2 gz = *(const float2*)&s_z[1536 + j];
    float2 cv = *(const float2*)(c + (size_t)row * 512 + j);
    float cn0 = sigm(fz.x) * cv.x + sigm(iz.x) * tanhf(gz.x);
    float cn1 = sigm(fz.y) * cv.y + sigm(iz.y) * tanhf(gz.y);
    *(float2*)(outC + (size_t)row * 512 + j) = make_float2(cn0, cn1);

    float sum2 = cn0 + cn1, sq2 = cn0 * cn0 + cn1 * cn1;
    #pragma unroll
    for (int o = 16; o; o >>= 1) {
        sum2 += __shfl_xor_sync(0xFFFFFFFFu, sum2, o);
        sq2  += __shfl_xor_sync(0xFFFFFFFFu, sq2, o);
    }
    if (lane == 0) { s_sum2[w] = sum2; s_sq2[w] = sq2; }
    __syncthreads();

    float ts = 0.0f, tq = 0.0f;
    #pragma unroll
    for (int k = 0; k < 8; k++) { ts += s_sum2[k]; tq += s_sq2[k]; }
    const float m2 = ts * (1.0f / 512.0f);
    const float v2 = tq * (1.0f / 512.0f) - m2 * m2;
    const float inv2 = rsqrtf(v2 + 1e-5f);
    float2 gm = *(const float2*)(gamma + j);
    float2 bt = *(const float2*)(beta + j);
    float cnn0 = (cn0 - m2) * inv2 * gm.x + bt.x;
    float cnn1 = (cn1 - m2) * inv2 * gm.y + bt.y;
    float2 oz = *(const float2*)&s_z[1024 + j];
    float h0 = sigm(oz.x) * tanhf(cnn0);
    float h1 = sigm(oz.y) * tanhf(cnn1);
    *(float2*)(outH + (size_t)row * 512 + j) = make_float2(h0, h1);
}

// ============================================================================
// kernel_launch
// ============================================================================
extern "C" void kernel_launch(void* const* d_in, const int* in_sizes, int n_in,
                              void* d_out, int out_size) {
    const float* x     = (const float*)d_in[0];
    const float* h     = (const float*)d_in[1];
    const float* c     = (const float*)d_in[2];
    const float* u     = (const float*)d_in[3];
    const float* W     = (const float*)d_in[4];
    const float* blin  = (const float*)d_in[5];
    const float* gamma = (const float*)d_in[6];
    const float* beta  = (const float*)d_in[7];
    float* outH = (float*)d_out;
    float* outC = (float*)d_out + (size_t)BROWS * HDIM;

    cudaFuncSetAttribute(gemm_mma_kernel,
                         cudaFuncAttributeMaxDynamicSharedMemorySize, GEMM_SMEM);

    prep_A_kernel<<<BROWS, 256>>>(x, h);
    prep_W_kernel<<<dim3(NDIM / 32, KDIM / 32), dim3(32, 8)>>>(W);
    gemm_mma_kernel<<<dim3(NDIM / BN, BROWS / BM), 256, GEMM_SMEM>>>(blin);
    fused_tail_kernel<<<BROWS, 256>>>(c, u, gamma, beta, outH, outC);
}

// round 6
// speedup vs baseline: 1.6821x; 1.0060x over previous
#include <cuda_runtime.h>
#include <cuda_fp16.h>
#include <cstdint>
#include <math.h>

// ============================================================================
// FiLMLSTMCell: B=16384, D_IN=512, H=512
// GEMM M=16384, N=2048, K=1024 via mma.sync m16n8k16 fp16 (f32 acc).
// HMMA rt ~= 12 cyc/SMSP measured -> compute floor ~179us; this round removes
// barrier/latency overheads around it (BK=128, 2-stage, 8 syncs) and hides
// tail load latency behind the GN reductions.
// ============================================================================
#define BROWS 16384
#define KDIM  1024
#define NDIM  2048
#define HDIM  512

__device__ __half g_Ah [(size_t)BROWS * KDIM];  // 32 MB : fp16 cat(x,h)
__device__ __half g_WTh[(size_t)NDIM * KDIM];   //  4 MB : fp16 W^T [N,K]
__device__ __half g_Zh [(size_t)BROWS * NDIM];  // 64 MB : fp16 z

__device__ __forceinline__ void mma_f16(float* c,
                                        uint32_t a0, uint32_t a1, uint32_t a2, uint32_t a3,
                                        uint32_t b0, uint32_t b1) {
    asm volatile(
        "mma.sync.aligned.m16n8k16.row.col.f32.f16.f16.f32 "
        "{%0,%1,%2,%3}, {%4,%5,%6,%7}, {%8,%9}, {%0,%1,%2,%3};"
        : "+f"(c[0]), "+f"(c[1]), "+f"(c[2]), "+f"(c[3])
        : "r"(a0), "r"(a1), "r"(a2), "r"(a3), "r"(b0), "r"(b1));
}

__device__ __forceinline__ void ldsm_x4(uint32_t& r0, uint32_t& r1,
                                        uint32_t& r2, uint32_t& r3, uint32_t addr) {
    asm volatile("ldmatrix.sync.aligned.m8n8.x4.shared.b16 {%0,%1,%2,%3}, [%4];"
                 : "=r"(r0), "=r"(r1), "=r"(r2), "=r"(r3) : "r"(addr));
}

// ============================================================================
// GEMM: CTA 128(M) x 256(N), BK=128 halves (256B rows), 256 threads
// (8 warps, 2Mx4N, warp tile 64x64), 2-stage cp.async, 8 chunks -> 8 syncs.
// smem word offset (row, kp 0..63): row*64 + (kp ^ (4*(row&7)))
// -> conflict-free LDSM, 16B groups preserved for cp.async.
// ============================================================================
#define BM 128
#define BN 256
#define BKH 128
#define NCHUNK (KDIM / BKH)       // 8
#define STAGES 2

#define A_WORDS (BM * BKH / 2)                 // 8192 (32-bit words, 32KB)
#define B_WORDS (BN * BKH / 2)                 // 16384 (64KB)
#define B_BASE  (STAGES * A_WORDS)             // 16384
#define BIAS_BASE (B_BASE + STAGES * B_WORDS)  // 49152
#define GEMM_SMEM ((BIAS_BASE + BN) * 4)       // 197632 B

__device__ __forceinline__ void load_chunk(uint32_t aBase, uint32_t bBase,
                                           const __half* __restrict__ Asrc,
                                           const __half* __restrict__ Bsrc,
                                           int tid) {
    // A tile: 128 rows x 16 (16B chunks) = 2048 tasks
    #pragma unroll
    for (int rep = 0; rep < 8; rep++) {
        int idx = rep * 256 + tid;
        int row = idx >> 4, q = idx & 15;
        uint32_t off = (uint32_t)(row * 256 + 16 * (q ^ (row & 7)));
        asm volatile("cp.async.cg.shared.global [%0], [%1], 16;"
                     :: "r"(aBase + off), "l"(Asrc + (size_t)row * KDIM + q * 8));
    }
    // B tile: 256 rows x 16 = 4096 tasks
    #pragma unroll
    for (int rep = 0; rep < 16; rep++) {
        int idx = rep * 256 + tid;
        int row = idx >> 4, q = idx & 15;
        uint32_t off = (uint32_t)(row * 256 + 16 * (q ^ (row & 7)));
        asm volatile("cp.async.cg.shared.global [%0], [%1], 16;"
                     :: "r"(bBase + off), "l"(Bsrc + (size_t)row * KDIM + q * 8));
    }
    asm volatile("cp.async.commit_group;" ::: "memory");
}

__global__ void __launch_bounds__(256, 1)
gemm_mma_kernel(const float* __restrict__ bias) {
    extern __shared__ float sm[];
    float* sBias = sm + BIAS_BASE;

    const int tid = threadIdx.x, wid = tid >> 5, lane = tid & 31;
    const int g = lane >> 2, l4 = lane & 3;
    const int m0 = blockIdx.y * BM;
    const int n0 = blockIdx.x * BN;
    const int wm = wid & 1, wn = wid >> 1;

    uint32_t sb;
    asm("{ .reg .u64 t; cvta.to.shared.u64 t, %1; cvt.u32.u64 %0, t; }"
        : "=r"(sb) : "l"(sm));

    for (int i = tid; i < BN; i += 256) sBias[i] = bias[n0 + i];

    // ldmatrix per-lane constants
    const int t8 = lane >> 3, rr = lane & 7;
    const int swz = 4 * rr;
    const int rowA = wm * 64 + (t8 & 1) * 8 + rr;     // + ms*16
    const int kselA = (t8 >> 1) * 4;
    const int rowB = wn * 64 + (t8 >> 1) * 8 + rr;    // + ns2*16
    const int kselB = (t8 & 1) * 4;

    float acc[4][8][4];
    #pragma unroll
    for (int a = 0; a < 4; a++)
        #pragma unroll
        for (int b = 0; b < 8; b++)
            #pragma unroll
            for (int d = 0; d < 4; d++) acc[a][b][d] = 0.0f;

    const __half* Ag = g_Ah  + (size_t)m0 * KDIM;
    const __half* Bg = g_WTh + (size_t)n0 * KDIM;

    // prologue: stage 0
    load_chunk(sb, sb + B_BASE * 4, Ag, Bg, tid);

    for (int kc = 0; kc < NCHUNK; kc++) {
        const int s = kc & 1;
        asm volatile("cp.async.wait_group 0;" ::: "memory");
        __syncthreads();

        if (kc + 1 < NCHUNK) {
            const int sl = (kc + 1) & 1;
            load_chunk(sb + sl * A_WORDS * 4, sb + (B_BASE + sl * B_WORDS) * 4,
                       Ag + (kc + 1) * BKH, Bg + (kc + 1) * BKH, tid);
        }

        const uint32_t aSm = sb + (uint32_t)s * A_WORDS * 4;
        const uint32_t bSm = sb + (uint32_t)(B_BASE + s * B_WORDS) * 4;

        #pragma unroll
        for (int ks = 0; ks < 8; ks++) {
            const int kwA = (ks * 8 + kselA) ^ swz;
            const int kwB = (ks * 8 + kselB) ^ swz;
            uint32_t afr[4][4];
            #pragma unroll
            for (int ms = 0; ms < 4; ms++)
                ldsm_x4(afr[ms][0], afr[ms][1], afr[ms][2], afr[ms][3],
                        aSm + 4u * ((rowA + ms * 16) * 64 + kwA));
            uint32_t bfr[8][2];
            #pragma unroll
            for (int ns2 = 0; ns2 < 4; ns2++)
                ldsm_x4(bfr[2 * ns2][0], bfr[2 * ns2][1],
                        bfr[2 * ns2 + 1][0], bfr[2 * ns2 + 1][1],
                        bSm + 4u * ((rowB + ns2 * 16) * 64 + kwB));
            #pragma unroll
            for (int ms = 0; ms < 4; ms++)
                #pragma unroll
                for (int ns = 0; ns < 8; ns++)
                    mma_f16(acc[ms][ns], afr[ms][0], afr[ms][1], afr[ms][2], afr[ms][3],
                            bfr[ns][0], bfr[ns][1]);
        }
    }

    // Epilogue: + bias, fp16 z store
    #pragma unroll
    for (int ms = 0; ms < 4; ms++) {
        const int row = m0 + wm * 64 + ms * 16 + g;
        #pragma unroll
        for (int ns = 0; ns < 8; ns++) {
            const int colL = wn * 64 + ns * 8 + 2 * l4;
            const float b0 = sBias[colL], b1 = sBias[colL + 1];
            __half2 v0 = __floats2half2_rn(acc[ms][ns][0] + b0, acc[ms][ns][1] + b1);
            __half2 v1 = __floats2half2_rn(acc[ms][ns][2] + b0, acc[ms][ns][3] + b1);
            *(__half2*)(g_Zh + (size_t)row       * NDIM + n0 + colL) = v0;
            *(__half2*)(g_Zh + (size_t)(row + 8) * NDIM + n0 + colL) = v1;
        }
    }
}

// ============================================================================
// Prep
// ============================================================================
__global__ void __launch_bounds__(256) prep_A_kernel(const float* __restrict__ x,
                                                     const float* __restrict__ h) {
    const int m = blockIdx.x, t = threadIdx.x;
    float4 v;
    if (t < 128) v = ((const float4*)(x + (size_t)m * 512))[t];
    else         v = ((const float4*)(h + (size_t)m * 512))[t - 128];
    __half2 lo = __floats2half2_rn(v.x, v.y);
    __half2 hi = __floats2half2_rn(v.z, v.w);
    uint2 pk = make_uint2(*(uint32_t*)&lo, *(uint32_t*)&hi);
    ((uint2*)(g_Ah + (size_t)m * KDIM))[t] = pk;
}

__global__ void prep_W_kernel(const float* __restrict__ W) {
    __shared__ float tile[32][33];
    const int n0 = blockIdx.x * 32, k0 = blockIdx.y * 32;
    const int tx = threadIdx.x, ty = threadIdx.y;
    #pragma unroll
    for (int j = 0; j < 32; j += 8)
        tile[ty + j][tx] = W[(size_t)(k0 + ty + j) * NDIM + n0 + tx];
    __syncthreads();
    #pragma unroll
    for (int j = 0; j < 32; j += 8)
        g_WTh[(size_t)(n0 + ty + j) * KDIM + k0 + tx] = __float2half_rn(tile[tx][ty + j]);
}

// ============================================================================
// Fused tail: all global loads hoisted above the reductions (MLP batching);
// GN(4)+FiLM+gates+c_new+GN(1)+h_new, 1 CTA / row.
// ============================================================================
__device__ __forceinline__ float sigm(float x) { return 1.0f / (1.0f + expf(-x)); }

__global__ void __launch_bounds__(256) fused_tail_kernel(
    const float* __restrict__ c, const float* __restrict__ u,
    const float* __restrict__ gamma, const float* __restrict__ beta,
    float* __restrict__ outH, float* __restrict__ outC) {
    __shared__ float s_z[2048];
    __shared__ float s_sum[8], s_sq[8], s_sum2[8], s_sq2[8];

    const int row = blockIdx.x;
    const int t = threadIdx.x, w = t >> 5, lane = t & 31;
    const int j = 2 * t;

    // ---- Issue ALL global loads up front (independent; overlap reductions)
    uint4 zp = ((const uint4*)(g_Zh + (size_t)row * 2048))[t];
    const float4* ua = (const float4*)(u + (size_t)row * 4096);
    const float4* ub = (const float4*)(u + (size_t)row * 4096 + 2048);
    float4 a0 = ua[2 * t], a1 = ua[2 * t + 1];
    float4 b0 = ub[2 * t], b1 = ub[2 * t + 1];
    float2 cv = *(const float2*)(c + (size_t)row * 512 + j);
    float2 gm = *(const float2*)(gamma + j);
    float2 bt = *(const float2*)(beta + j);

    float2 zf[4];
    zf[0] = __half22float2(*(__half2*)&zp.x);
    zf[1] = __half22float2(*(__half2*)&zp.y);
    zf[2] = __half22float2(*(__half2*)&zp.z);
    zf[3] = __half22float2(*(__half2*)&zp.w);

    // ---- GN(4) stats (thread t owns z[8t..8t+8); warp stays in one group)
    float sum = 0.0f, sq = 0.0f;
    #pragma unroll
    for (int q = 0; q < 4; q++) {
        sum += zf[q].x + zf[q].y;
        sq  += zf[q].x * zf[q].x + zf[q].y * zf[q].y;
    }
    #pragma unroll
    for (int o = 16; o; o >>= 1) {
        sum += __shfl_xor_sync(0xFFFFFFFFu, sum, o);
        sq  += __shfl_xor_sync(0xFFFFFFFFu, sq, o);
    }
    if (lane == 0) { s_sum[w] = sum; s_sq[w] = sq; }
    __syncthreads();
    const int grp = t >> 6;
    const float mean = (s_sum[2 * grp] + s_sum[2 * grp + 1]) * (1.0f / 512.0f);
    const float var  = (s_sq[2 * grp] + s_sq[2 * grp + 1]) * (1.0f / 512.0f) - mean * mean;
    const float inv  = rsqrtf(var + 1e-5f);

    float4 o0, o1;
    o0.x = (zf[0].x - mean) * inv * (1.0f + a0.x) + b0.x;
    o0.y = (zf[0].y - mean) * inv * (1.0f + a0.y) + b0.y;
    o0.z = (zf[1].x - mean) * inv * (1.0f + a0.z) + b0.z;
    o0.w = (zf[1].y - mean) * inv * (1.0f + a0.w) + b0.w;
    o1.x = (zf[2].x - mean) * inv * (1.0f + a1.x) + b1.x;
    o1.y = (zf[2].y - mean) * inv * (1.0f + a1.y) + b1.y;
    o1.z = (zf[3].x - mean) * inv * (1.0f + a1.z) + b1.z;
    o1.w = (zf[3].y - mean) * inv * (1.0f + a1.w) + b1.w;
    ((float4*)s_z)[2 * t] = o0;
    ((float4*)s_z)[2 * t + 1] = o1;
    __syncthreads();

    // ---- gates -> c_new
    float2 iz = *(const float2*)&s_z[j];
    float2 fz = *(const float2*)&s_z[512 + j];
    float2 gz = *(const float2*)&s_z[1536 + j];
    float cn0 = sigm(fz.x) * cv.x + sigm(iz.x) * tanhf(gz.x);
    float cn1 = sigm(fz.y) * cv.y + sigm(iz.y) * tanhf(gz.y);
    *(float2*)(outC + (size_t)row * 512 + j) = make_float2(cn0, cn1);

    float sum2 = cn0 + cn1, sq2 = cn0 * cn0 + cn1 * cn1;
    #pragma unroll
    for (int o = 16; o; o >>= 1) {
        sum2 += __shfl_xor_sync(0xFFFFFFFFu, sum2, o);
        sq2  += __shfl_xor_sync(0xFFFFFFFFu, sq2, o);
    }
    if (lane == 0) { s_sum2[w] = sum2; s_sq2[w] = sq2; }
    __syncthreads();

    // ---- GN(1) over c_new, then h_new
    float ts = 0.0f, tq = 0.0f;
    #pragma unroll
    for (int k = 0; k < 8; k++) { ts += s_sum2[k]; tq += s_sq2[k]; }
    const float m2 = ts * (1.0f / 512.0f);
    const float v2 = tq * (1.0f / 512.0f) - m2 * m2;
    const float inv2 = rsqrtf(v2 + 1e-5f);
    float cnn0 = (cn0 - m2) * inv2 * gm.x + bt.x;
    float cnn1 = (cn1 - m2) * inv2 * gm.y + bt.y;
    float2 oz = *(const float2*)&s_z[1024 + j];
    float h0 = sigm(oz.x) * tanhf(cnn0);
    float h1 = sigm(oz.y) * tanhf(cnn1);
    *(float2*)(outH + (size_t)row * 512 + j) = make_float2(h0, h1);
}

// ============================================================================
// kernel_launch
// ============================================================================
extern "C" void kernel_launch(void* const* d_in, const int* in_sizes, int n_in,
                              void* d_out, int out_size) {
    const float* x     = (const float*)d_in[0];
    const float* h     = (const float*)d_in[1];
    const float* c     = (const float*)d_in[2];
    const float* u     = (const float*)d_in[3];
    const float* W     = (const float*)d_in[4];
    const float* blin  = (const float*)d_in[5];
    const float* gamma = (const float*)d_in[6];
    const float* beta  = (const float*)d_in[7];
    float* outH = (float*)d_out;
    float* outC = (float*)d_out + (size_t)BROWS * HDIM;

    cudaFuncSetAttribute(gemm_mma_kernel,
                         cudaFuncAttributeMaxDynamicSharedMemorySize, GEMM_SMEM);

    prep_A_kernel<<<BROWS, 256>>>(x, h);
    prep_W_kernel<<<dim3(NDIM / 32, KDIM / 32), dim3(32, 8)>>>(W);
    gemm_mma_kernel<<<dim3(NDIM / BN, BROWS / BM), 256, GEMM_SMEM>>>(blin);
    fused_tail_kernel<<<BROWS, 256>>>(c, u, gamma, beta, outH, outC);
}